// round 2
// baseline (speedup 1.0000x reference)
#include <cuda_runtime.h>
#include <cuda_bf16.h>
#include <cstdint>

// ---------------------------------------------------------------------------
// Problem shape (fixed by the dataset instance)
// ---------------------------------------------------------------------------
#define B_SZ   4
#define N_DOWN 4096      // points per batch in the downsampled cloud
#define N_UP   16384     // points per batch in the upsampled cloud
#define C_IN   256
#define C_OUT  128
#define KNN    4

#define M_DOWN (B_SZ * N_DOWN)   // 16384 rows for the down MLP
#define M_UP   (B_SZ * N_UP)     // 65536 rows for the up MLP

// ---------------------------------------------------------------------------
// Device-global scratch (allocation-free per harness rules)
// ---------------------------------------------------------------------------
__device__ float g_xd[M_DOWN * C_OUT];        // 8 MB: relu(bn(x_down @ W_down))
__device__ int   g_knn_idx[M_UP * KNN];       // 1 MB
__device__ float g_knn_w[M_UP * KNN];         // 1 MB: normalized inverse-d2 weights

// ---------------------------------------------------------------------------
// Kernel 2: brute-force K=4 nearest neighbors.
// CRITICAL: distance formula must match the reference's gram-trick numerics:
//   d2 = (|q|^2 + |p|^2) - 2*(q . p)
// computed in fp32 with the same cancellation behavior, NOT the (more
// accurate) direct (dx^2+dy^2+dz^2) form — otherwise near-tie neighbor
// selections flip vs the reference and rel_err lands ~1e-3.
// grid = (N_UP/256, B), block = 256
// ---------------------------------------------------------------------------
__global__ void __launch_bounds__(256) knn_kernel(const float* __restrict__ p_down,
                                                  const float* __restrict__ p_up)
{
    __shared__ float sx[N_DOWN];
    __shared__ float sy[N_DOWN];
    __shared__ float sz[N_DOWN];
    __shared__ float spp[N_DOWN];   // |p|^2, computed like jnp.sum(p*p): (x*x + y*y) + z*z

    const int b = blockIdx.y;
    const float* pd = p_down + (size_t)b * N_DOWN * 3;
    for (int t = threadIdx.x; t < N_DOWN; t += 256) {
        const float px = pd[t * 3 + 0];
        const float py = pd[t * 3 + 1];
        const float pz = pd[t * 3 + 2];
        sx[t] = px;
        sy[t] = py;
        sz[t] = pz;
        // no fma contraction: plain mul/add, matching elementwise square + sum
        spp[t] = __fadd_rn(__fadd_rn(__fmul_rn(px, px), __fmul_rn(py, py)),
                           __fmul_rn(pz, pz));
    }
    __syncthreads();

    const int q = blockIdx.x * 256 + threadIdx.x;      // query within batch
    const int r = b * N_UP + q;                        // global query row
    const float qx = p_up[(size_t)r * 3 + 0];
    const float qy = p_up[(size_t)r * 3 + 1];
    const float qz = p_up[(size_t)r * 3 + 2];
    const float qq = __fadd_rn(__fadd_rn(__fmul_rn(qx, qx), __fmul_rn(qy, qy)),
                               __fmul_rn(qz, qz));

    float bd0 = 1e30f, bd1 = 1e30f, bd2 = 1e30f, bd3 = 1e30f;
    int   bi0 = 0,     bi1 = 0,     bi2 = 0,     bi3 = 0;

    #pragma unroll 4
    for (int j = 0; j < N_DOWN; j++) {
        // dot product as a GEMM would: fma chain
        float dot = __fmul_rn(qx, sx[j]);
        dot = fmaf(qy, sy[j], dot);
        dot = fmaf(qz, sz[j], dot);
        // (qq + pp) - 2*dot, separate ops (no contraction)
        const float d2 = __fadd_rn(__fadd_rn(qq, spp[j]),
                                   -__fmul_rn(2.0f, dot));
        if (d2 < bd3) {
            if (d2 < bd2) {
                bd3 = bd2; bi3 = bi2;
                if (d2 < bd1) {
                    bd2 = bd1; bi2 = bi1;
                    if (d2 < bd0) {
                        bd1 = bd0; bi1 = bi0;
                        bd0 = d2;  bi0 = j;
                    } else {
                        bd1 = d2; bi1 = j;
                    }
                } else {
                    bd2 = d2; bi2 = j;
                }
            } else {
                bd3 = d2; bi3 = j;
            }
        }
    }

    // max(d2, 0) then clip to 1e-16 == max(d2, 1e-16)
    const float w0 = 1.0f / fmaxf(bd0, 1e-16f);
    const float w1 = 1.0f / fmaxf(bd1, 1e-16f);
    const float w2 = 1.0f / fmaxf(bd2, 1e-16f);
    const float w3 = 1.0f / fmaxf(bd3, 1e-16f);
    const float inv = 1.0f / (((w0 + w1) + w2) + w3);

    g_knn_idx[r * 4 + 0] = bi0;
    g_knn_idx[r * 4 + 1] = bi1;
    g_knn_idx[r * 4 + 2] = bi2;
    g_knn_idx[r * 4 + 3] = bi3;
    g_knn_w[r * 4 + 0] = w0 * inv;
    g_knn_w[r * 4 + 1] = w1 * inv;
    g_knn_w[r * 4 + 2] = w2 * inv;
    g_knn_w[r * 4 + 3] = w3 * inv;
}

// ---------------------------------------------------------------------------
// Register-tiled fp32 GEMM + BN + ReLU.  C = relu(bn(A[M,K] @ W[K,128])).
// BM=128, BN=128 (=C_OUT exactly), BK=16, 256 threads, 8x8 per thread.
// FUSED=false : write result to g_xd (down MLP).
// FUSED=true  : add the kNN-interpolated feature (gathered from g_xd with
//               normalized weights) and write to `out` (up MLP + final add).
// ---------------------------------------------------------------------------
#define BM 128
#define BN 128
#define BK 16
#define TM 8
#define TN 8

template <bool FUSED>
__global__ void __launch_bounds__(256) gemm_bn_relu_kernel(
    const float* __restrict__ A,
    const float* __restrict__ W,
    const float* __restrict__ bias,
    const float* __restrict__ gamma,
    const float* __restrict__ beta,
    const float* __restrict__ mean,
    const float* __restrict__ var,
    float* __restrict__ out,
    int Kdim)
{
    __shared__ float As[BK][BM];
    __shared__ float Bs[BK][BN];

    const int tid  = threadIdx.x;
    const int tx   = tid & 15;        // 0..15 : column group
    const int ty   = tid >> 4;        // 0..15 : row group
    const int row0 = blockIdx.x * BM;

    float acc[TM][TN];
    #pragma unroll
    for (int i = 0; i < TM; i++)
        #pragma unroll
        for (int j = 0; j < TN; j++) acc[i][j] = 0.0f;

    for (int kt = 0; kt < Kdim; kt += BK) {
        // Load A tile: BM x BK = 2048 floats = 512 float4, 2 per thread.
        #pragma unroll
        for (int i = 0; i < 2; i++) {
            const int f  = tid + i * 256;        // 0..511
            const int rr = f >> 2;               // tile row 0..127
            const int kq = (f & 3) * 4;          // k offset 0,4,8,12
            const float4 av = *(const float4*)(A + (size_t)(row0 + rr) * Kdim + kt + kq);
            As[kq + 0][rr] = av.x;
            As[kq + 1][rr] = av.y;
            As[kq + 2][rr] = av.z;
            As[kq + 3][rr] = av.w;
        }
        // Load W tile: BK x BN = 2048 floats, row-major, 2 float4 per thread.
        #pragma unroll
        for (int i = 0; i < 2; i++) {
            const int f  = tid + i * 256;
            const int kr = f >> 5;               // 0..15
            const int cc = (f & 31) * 4;         // 0..124
            *(float4*)&Bs[kr][cc] = *(const float4*)(W + (size_t)(kt + kr) * BN + cc);
        }
        __syncthreads();

        #pragma unroll
        for (int k = 0; k < BK; k++) {
            float a[TM], bb[TN];
            const float4 a0 = *(const float4*)&As[k][ty * TM];
            const float4 a1 = *(const float4*)&As[k][ty * TM + 4];
            a[0] = a0.x; a[1] = a0.y; a[2] = a0.z; a[3] = a0.w;
            a[4] = a1.x; a[5] = a1.y; a[6] = a1.z; a[7] = a1.w;
            const float4 b0 = *(const float4*)&Bs[k][tx * TN];
            const float4 b1 = *(const float4*)&Bs[k][tx * TN + 4];
            bb[0] = b0.x; bb[1] = b0.y; bb[2] = b0.z; bb[3] = b0.w;
            bb[4] = b1.x; bb[5] = b1.y; bb[6] = b1.z; bb[7] = b1.w;
            #pragma unroll
            for (int i = 0; i < TM; i++)
                #pragma unroll
                for (int j = 0; j < TN; j++)
                    acc[i][j] = fmaf(a[i], bb[j], acc[i][j]);
        }
        __syncthreads();
    }

    // BN fold: z = acc*scale + shift, scale = g*rsqrt(v+eps), shift = be + (b-m)*scale
    float scale[TN], shift[TN];
    #pragma unroll
    for (int j = 0; j < TN; j++) {
        const int c = tx * TN + j;
        const float s = gamma[c] * rsqrtf(var[c] + 1e-5f);
        scale[j] = s;
        shift[j] = beta[c] + (bias[c] - mean[c]) * s;
    }

    #pragma unroll
    for (int i = 0; i < TM; i++) {
        const int r = row0 + ty * TM + i;          // global output row
        float interp[TN];
        #pragma unroll
        for (int j = 0; j < TN; j++) interp[j] = 0.0f;

        if (FUSED) {
            const int bidx = r >> 14;              // r / N_UP  (N_UP = 16384)
            const float* xdb = g_xd + (size_t)bidx * N_DOWN * C_OUT;
            #pragma unroll
            for (int k = 0; k < KNN; k++) {
                const int   id = g_knn_idx[r * 4 + k];
                const float wk = g_knn_w[r * 4 + k];
                const float* frow = xdb + (size_t)id * C_OUT + tx * TN;
                #pragma unroll
                for (int j = 0; j < TN; j++)
                    interp[j] = fmaf(wk, frow[j], interp[j]);
            }
        }

        float* dst = FUSED ? out : g_xd;
        float res[TN];
        #pragma unroll
        for (int j = 0; j < TN; j++) {
            float z = fmaf(acc[i][j], scale[j], shift[j]);
            z = fmaxf(z, 0.0f);
            res[j] = z + interp[j];
        }
        // two float4 stores per row
        *(float4*)(dst + (size_t)r * C_OUT + tx * TN)     = make_float4(res[0], res[1], res[2], res[3]);
        *(float4*)(dst + (size_t)r * C_OUT + tx * TN + 4) = make_float4(res[4], res[5], res[6], res[7]);
    }
}

// ---------------------------------------------------------------------------
// Launch
// ---------------------------------------------------------------------------
extern "C" void kernel_launch(void* const* d_in, const int* in_sizes, int n_in,
                              void* d_out, int out_size)
{
    const float* x_down  = (const float*)d_in[0];
    const float* x_up    = (const float*)d_in[1];
    const float* p_down  = (const float*)d_in[2];
    const float* p_up    = (const float*)d_in[3];
    const float* W_down  = (const float*)d_in[4];
    const float* b_down  = (const float*)d_in[5];
    const float* g_down  = (const float*)d_in[6];
    const float* be_down = (const float*)d_in[7];
    const float* m_down  = (const float*)d_in[8];
    const float* v_down  = (const float*)d_in[9];
    const float* W_up    = (const float*)d_in[10];
    const float* b_up    = (const float*)d_in[11];
    const float* g_up    = (const float*)d_in[12];
    const float* be_up   = (const float*)d_in[13];
    const float* m_up    = (const float*)d_in[14];
    const float* v_up    = (const float*)d_in[15];
    float* out = (float*)d_out;

    // 1) down MLP -> g_xd   (M=16384, K=256)
    gemm_bn_relu_kernel<false><<<M_DOWN / BM, 256>>>(
        x_down, W_down, b_down, g_down, be_down, m_down, v_down,
        nullptr, C_IN);

    // 2) kNN
    dim3 knn_grid(N_UP / 256, B_SZ);
    knn_kernel<<<knn_grid, 256>>>(p_down, p_up);

    // 3) up MLP + interpolation gather + add -> out   (M=65536, K=128)
    gemm_bn_relu_kernel<true><<<M_UP / BM, 256>>>(
        x_up, W_up, b_up, g_up, be_up, m_up, v_up,
        out, C_OUT);
}

// round 3
// speedup vs baseline: 1.0402x; 1.0402x over previous
#include <cuda_runtime.h>
#include <cuda_bf16.h>
#include <cstdint>

// ---------------------------------------------------------------------------
// Problem shape (fixed by the dataset instance)
// ---------------------------------------------------------------------------
#define B_SZ   4
#define N_DOWN 4096
#define N_UP   16384
#define C_IN   256
#define C_OUT  128
#define KNN    4

#define M_DOWN (B_SZ * N_DOWN)   // 16384
#define M_UP   (B_SZ * N_UP)     // 65536

// Spatial grid for kNN: 8x8x8 over [0,1]^3, ~8 points/cell
#define G      8
#define NCELL  (G * G * G)       // 512
#define GH     0.125f            // cell edge

// ---------------------------------------------------------------------------
// Device-global scratch
// ---------------------------------------------------------------------------
__device__ float g_xd[M_DOWN * C_OUT];            // 8 MB
__device__ int   g_knn_idx[M_UP * KNN];
__device__ float g_knn_w[M_UP * KNN];
__device__ float4         g_pts[B_SZ][N_DOWN];    // sorted (x,y,z,|p|^2)
__device__ unsigned short g_ptid[B_SZ][N_DOWN];   // sorted -> original index
__device__ int            g_cellstart[B_SZ][NCELL + 1];

// ---------------------------------------------------------------------------
// Grid build: one block per batch, 512 threads, 8 points/thread.
// count -> scan -> scatter, all in shared memory.
// ---------------------------------------------------------------------------
__global__ void __launch_bounds__(512) build_grid(const float* __restrict__ p_down)
{
    __shared__ int counts[NCELL];
    __shared__ int s1[NCELL];
    __shared__ int s2[NCELL];

    const int b = blockIdx.x;
    const int t = threadIdx.x;
    const float* pd = p_down + (size_t)b * N_DOWN * 3;

    counts[t] = 0;
    __syncthreads();

    float px[8], py[8], pz[8];
    int   cid[8];
    #pragma unroll
    for (int i = 0; i < 8; i++) {
        const int j = i * 512 + t;
        px[i] = pd[j * 3 + 0];
        py[i] = pd[j * 3 + 1];
        pz[i] = pd[j * 3 + 2];
        const int cx = min(G - 1, (int)(px[i] * (float)G));
        const int cy = min(G - 1, (int)(py[i] * (float)G));
        const int cz = min(G - 1, (int)(pz[i] * (float)G));
        cid[i] = cx | (cy << 3) | (cz << 6);
        atomicAdd(&counts[cid[i]], 1);
    }
    __syncthreads();

    // inclusive scan over 512 counts (Hillis-Steele, ping-pong)
    s1[t] = counts[t];
    __syncthreads();
    int* src = s1;
    int* dst = s2;
    for (int d = 1; d < NCELL; d <<= 1) {
        int v = src[t];
        if (t >= d) v += src[t - d];
        dst[t] = v;
        __syncthreads();
        int* tmp = src; src = dst; dst = tmp;
    }
    const int excl = src[t] - counts[t];
    g_cellstart[b][t] = excl;
    if (t == 0) g_cellstart[b][NCELL] = N_DOWN;
    counts[t] = excl;   // reuse as scatter cursor
    __syncthreads();

    #pragma unroll
    for (int i = 0; i < 8; i++) {
        const int j = i * 512 + t;
        const int slot = atomicAdd(&counts[cid[i]], 1);
        // |p|^2 exactly as reference: (x*x + y*y) + z*z, no fma contraction
        const float pp = __fadd_rn(__fadd_rn(__fmul_rn(px[i], px[i]),
                                             __fmul_rn(py[i], py[i])),
                                   __fmul_rn(pz[i], pz[i]));
        g_pts[b][slot]  = make_float4(px[i], py[i], pz[i], pp);
        g_ptid[b][slot] = (unsigned short)j;
    }
}

// ---------------------------------------------------------------------------
// kNN query: one thread per query. Batch's sorted points live in smem.
// Distance numerics EXACTLY match the reference gram trick:
//   d2 = (qq + pp) - 2*dot, dot = fma chain.
// Expanding-shell search with bound: unprocessed cells at Chebyshev >= r
// have d >= (r-1)*GH, so after processing Chebyshev <= r-1 we may stop when
// bd3 <= ((r-1)*GH)^2.
// ---------------------------------------------------------------------------
#define SMEM_Q (N_DOWN * 16 + N_DOWN * 2 + (NCELL + 1) * 4)

__global__ void __launch_bounds__(256) knn_query(const float* __restrict__ p_up)
{
    extern __shared__ char sm[];
    float4*         spts   = (float4*)sm;
    unsigned short* sid    = (unsigned short*)(sm + N_DOWN * 16);
    int*            cstart = (int*)(sm + N_DOWN * 16 + N_DOWN * 2);

    const int b = blockIdx.y;
    for (int i = threadIdx.x; i < N_DOWN; i += 256) spts[i] = g_pts[b][i];
    for (int i = threadIdx.x; i < N_DOWN; i += 256) sid[i] = g_ptid[b][i];
    for (int i = threadIdx.x; i <= NCELL; i += 256) cstart[i] = g_cellstart[b][i];
    __syncthreads();

    const int q = blockIdx.x * 256 + threadIdx.x;
    const int r = b * N_UP + q;
    const float qx = p_up[(size_t)r * 3 + 0];
    const float qy = p_up[(size_t)r * 3 + 1];
    const float qz = p_up[(size_t)r * 3 + 2];
    const float qq = __fadd_rn(__fadd_rn(__fmul_rn(qx, qx), __fmul_rn(qy, qy)),
                               __fmul_rn(qz, qz));
    const int cx = min(G - 1, (int)(qx * (float)G));
    const int cy = min(G - 1, (int)(qy * (float)G));
    const int cz = min(G - 1, (int)(qz * (float)G));

    float bd0 = 1e30f, bd1 = 1e30f, bd2 = 1e30f, bd3 = 1e30f;
    int   s0 = 0, s1_ = 0, s2_ = 0, s3 = 0;

    #define SCAN_CELL(cell)                                                     \
    {                                                                           \
        const int e_ = cstart[(cell) + 1];                                      \
        for (int k_ = cstart[(cell)]; k_ < e_; k_++) {                          \
            const float4 p_ = spts[k_];                                         \
            float dot_ = __fmul_rn(qx, p_.x);                                   \
            dot_ = fmaf(qy, p_.y, dot_);                                        \
            dot_ = fmaf(qz, p_.z, dot_);                                        \
            const float d2_ = __fadd_rn(__fadd_rn(qq, p_.w),                    \
                                        -__fmul_rn(2.0f, dot_));                \
            if (d2_ < bd3) {                                                    \
                if (d2_ < bd2) {                                                \
                    bd3 = bd2; s3 = s2_;                                        \
                    if (d2_ < bd1) {                                            \
                        bd2 = bd1; s2_ = s1_;                                   \
                        if (d2_ < bd0) {                                        \
                            bd1 = bd0; s1_ = s0;                                \
                            bd0 = d2_; s0 = k_;                                 \
                        } else { bd1 = d2_; s1_ = k_; }                         \
                    } else { bd2 = d2_; s2_ = k_; }                             \
                } else { bd3 = d2_; s3 = k_; }                                  \
            }                                                                   \
        }                                                                       \
    }

    // Chebyshev <= 1 cube (clamped)
    {
        const int z0 = max(0, cz - 1), z1 = min(G - 1, cz + 1);
        const int y0 = max(0, cy - 1), y1 = min(G - 1, cy + 1);
        const int x0 = max(0, cx - 1), x1 = min(G - 1, cx + 1);
        for (int z = z0; z <= z1; z++)
            for (int y = y0; y <= y1; y++)
                for (int x = x0; x <= x1; x++)
                    SCAN_CELL(x | (y << 3) | (z << 6));
    }

    // expanding rings r = 2..7
    for (int rad = 2; rad < G; rad++) {
        const float dmin = (float)(rad - 1) * GH;
        if (bd3 <= dmin * dmin) break;
        const int z0 = max(0, cz - rad), z1 = min(G - 1, cz + rad);
        const int y0 = max(0, cy - rad), y1 = min(G - 1, cy + rad);
        const int x0 = max(0, cx - rad), x1 = min(G - 1, cx + rad);
        for (int z = z0; z <= z1; z++) {
            const int az = abs(z - cz);
            for (int y = y0; y <= y1; y++) {
                const int ay = abs(y - cy);
                for (int x = x0; x <= x1; x++) {
                    const int ax = abs(x - cx);
                    if (max(ax, max(ay, az)) == rad)
                        SCAN_CELL(x | (y << 3) | (z << 6));
                }
            }
        }
    }
    #undef SCAN_CELL

    const float w0 = 1.0f / fmaxf(bd0, 1e-16f);
    const float w1 = 1.0f / fmaxf(bd1, 1e-16f);
    const float w2 = 1.0f / fmaxf(bd2, 1e-16f);
    const float w3 = 1.0f / fmaxf(bd3, 1e-16f);
    const float inv = 1.0f / (((w0 + w1) + w2) + w3);

    g_knn_idx[r * 4 + 0] = (int)sid[s0];
    g_knn_idx[r * 4 + 1] = (int)sid[s1_];
    g_knn_idx[r * 4 + 2] = (int)sid[s2_];
    g_knn_idx[r * 4 + 3] = (int)sid[s3];
    g_knn_w[r * 4 + 0] = w0 * inv;
    g_knn_w[r * 4 + 1] = w1 * inv;
    g_knn_w[r * 4 + 2] = w2 * inv;
    g_knn_w[r * 4 + 3] = w3 * inv;
}

// ---------------------------------------------------------------------------
// Register-tiled fp32 GEMM + BN + ReLU.  C = relu(bn(A[M,K] @ W[K,128])).
// BM = 16*TM_, BN=128, BK=16, 256 threads, TM_ x 8 per thread.
// ---------------------------------------------------------------------------
#define BN 128
#define BK 16
#define TN 8

template <int TM_, bool FUSED>
__global__ void __launch_bounds__(256) gemm_bn_relu_kernel(
    const float* __restrict__ A,
    const float* __restrict__ W,
    const float* __restrict__ bias,
    const float* __restrict__ gamma,
    const float* __restrict__ beta,
    const float* __restrict__ mean,
    const float* __restrict__ var,
    float* __restrict__ out,
    int Kdim)
{
    constexpr int BM_ = 16 * TM_;
    __shared__ float As[BK][BM_];
    __shared__ float Bs[BK][BN];

    const int tid  = threadIdx.x;
    const int tx   = tid & 15;
    const int ty   = tid >> 4;
    const int row0 = blockIdx.x * BM_;

    float acc[TM_][TN];
    #pragma unroll
    for (int i = 0; i < TM_; i++)
        #pragma unroll
        for (int j = 0; j < TN; j++) acc[i][j] = 0.0f;

    for (int kt = 0; kt < Kdim; kt += BK) {
        // A tile: BM_ x BK floats = BM_*4 float4, (BM_/64) per thread
        #pragma unroll
        for (int i = 0; i < BM_ / 64; i++) {
            const int f  = tid + i * 256;
            const int rr = f >> 2;
            const int kq = (f & 3) * 4;
            const float4 av = *(const float4*)(A + (size_t)(row0 + rr) * Kdim + kt + kq);
            As[kq + 0][rr] = av.x;
            As[kq + 1][rr] = av.y;
            As[kq + 2][rr] = av.z;
            As[kq + 3][rr] = av.w;
        }
        // W tile: BK x BN = 512 float4, 2 per thread
        #pragma unroll
        for (int i = 0; i < 2; i++) {
            const int f  = tid + i * 256;
            const int kr = f >> 5;
            const int cc = (f & 31) * 4;
            *(float4*)&Bs[kr][cc] = *(const float4*)(W + (size_t)(kt + kr) * BN + cc);
        }
        __syncthreads();

        #pragma unroll
        for (int k = 0; k < BK; k++) {
            float a[TM_], bb[TN];
            #pragma unroll
            for (int i = 0; i < TM_ / 4; i++) {
                const float4 av = *(const float4*)&As[k][ty * TM_ + i * 4];
                a[i * 4 + 0] = av.x; a[i * 4 + 1] = av.y;
                a[i * 4 + 2] = av.z; a[i * 4 + 3] = av.w;
            }
            const float4 b0 = *(const float4*)&Bs[k][tx * TN];
            const float4 b1 = *(const float4*)&Bs[k][tx * TN + 4];
            bb[0] = b0.x; bb[1] = b0.y; bb[2] = b0.z; bb[3] = b0.w;
            bb[4] = b1.x; bb[5] = b1.y; bb[6] = b1.z; bb[7] = b1.w;
            #pragma unroll
            for (int i = 0; i < TM_; i++)
                #pragma unroll
                for (int j = 0; j < TN; j++)
                    acc[i][j] = fmaf(a[i], bb[j], acc[i][j]);
        }
        __syncthreads();
    }

    float scale[TN], shift[TN];
    #pragma unroll
    for (int j = 0; j < TN; j++) {
        const int c = tx * TN + j;
        const float s = gamma[c] * rsqrtf(var[c] + 1e-5f);
        scale[j] = s;
        shift[j] = beta[c] + (bias[c] - mean[c]) * s;
    }

    #pragma unroll
    for (int i = 0; i < TM_; i++) {
        const int r = row0 + ty * TM_ + i;
        float interp[TN];
        #pragma unroll
        for (int j = 0; j < TN; j++) interp[j] = 0.0f;

        if (FUSED) {
            const int bidx = r >> 14;
            const float* xdb = g_xd + (size_t)bidx * N_DOWN * C_OUT;
            #pragma unroll
            for (int k = 0; k < KNN; k++) {
                const int   id = g_knn_idx[r * 4 + k];
                const float wk = g_knn_w[r * 4 + k];
                const float* frow = xdb + (size_t)id * C_OUT + tx * TN;
                #pragma unroll
                for (int j = 0; j < TN; j++)
                    interp[j] = fmaf(wk, frow[j], interp[j]);
            }
        }

        float* dst = FUSED ? out : g_xd;
        float res[TN];
        #pragma unroll
        for (int j = 0; j < TN; j++) {
            float z = fmaf(acc[i][j], scale[j], shift[j]);
            z = fmaxf(z, 0.0f);
            res[j] = z + interp[j];
        }
        *(float4*)(dst + (size_t)r * C_OUT + tx * TN)     = make_float4(res[0], res[1], res[2], res[3]);
        *(float4*)(dst + (size_t)r * C_OUT + tx * TN + 4) = make_float4(res[4], res[5], res[6], res[7]);
    }
}

// ---------------------------------------------------------------------------
// Launch
// ---------------------------------------------------------------------------
extern "C" void kernel_launch(void* const* d_in, const int* in_sizes, int n_in,
                              void* d_out, int out_size)
{
    const float* x_down  = (const float*)d_in[0];
    const float* x_up    = (const float*)d_in[1];
    const float* p_down  = (const float*)d_in[2];
    const float* p_up    = (const float*)d_in[3];
    const float* W_down  = (const float*)d_in[4];
    const float* b_down  = (const float*)d_in[5];
    const float* g_down  = (const float*)d_in[6];
    const float* be_down = (const float*)d_in[7];
    const float* m_down  = (const float*)d_in[8];
    const float* v_down  = (const float*)d_in[9];
    const float* W_up    = (const float*)d_in[10];
    const float* b_up    = (const float*)d_in[11];
    const float* g_up    = (const float*)d_in[12];
    const float* be_up   = (const float*)d_in[13];
    const float* m_up    = (const float*)d_in[14];
    const float* v_up    = (const float*)d_in[15];
    float* out = (float*)d_out;

    static bool attr_done = false;
    if (!attr_done) {
        cudaFuncSetAttribute(knn_query, cudaFuncAttributeMaxDynamicSharedMemorySize, SMEM_Q);
        attr_done = true;
    }

    // 1) grid build + kNN
    build_grid<<<B_SZ, 512>>>(p_down);
    dim3 qgrid(N_UP / 256, B_SZ);
    knn_query<<<qgrid, 256, SMEM_Q>>>(p_up);

    // 2) down MLP -> g_xd   (M=16384, K=256), BM=64 -> 256 CTAs
    gemm_bn_relu_kernel<4, false><<<M_DOWN / 64, 256>>>(
        x_down, W_down, b_down, g_down, be_down, m_down, v_down,
        nullptr, C_IN);

    // 3) up MLP + gather + add -> out   (M=65536, K=128), BM=64 -> 1024 CTAs
    gemm_bn_relu_kernel<4, true><<<M_UP / 64, 256>>>(
        x_up, W_up, b_up, g_up, be_up, m_up, v_up,
        out, C_OUT);
}

// round 4
// speedup vs baseline: 1.3650x; 1.3122x over previous
#include <cuda_runtime.h>
#include <cuda_bf16.h>
#include <cstdint>

// ---------------------------------------------------------------------------
// Problem shape (fixed)
// ---------------------------------------------------------------------------
#define B_SZ   4
#define N_DOWN 4096
#define N_UP   16384
#define C_IN   256
#define C_OUT  128
#define KNN    4

#define M_DOWN (B_SZ * N_DOWN)   // 16384
#define M_UP   (B_SZ * N_UP)     // 65536

// Spatial grid: 8x8x8 over [0,1]^3
#define G      8
#define NCELL  (G * G * G)       // 512
#define GH     0.125f

// ---------------------------------------------------------------------------
// Device-global scratch
// ---------------------------------------------------------------------------
__device__ float g_xd[M_DOWN * C_OUT];              // 8 MB
__device__ int   g_knn_idx[M_UP * KNN];
__device__ float g_knn_w[M_UP * KNN];
__device__ float4         g_pts[B_SZ][N_DOWN];      // cell-sorted (x,y,z,|p|^2)
__device__ unsigned short g_ptid[B_SZ][N_DOWN];     // sorted -> original index
__device__ int            g_cellstart[B_SZ][NCELL + 1];
__device__ unsigned short g_qid[B_SZ][N_UP];        // queries sorted by cell
__device__ int            g_qcellstart[B_SZ][NCELL + 1];

// ---------------------------------------------------------------------------
// Generic grid build: one block per batch, 512 threads.
// Two passes over the points (count, then scatter); scan in between.
// WRITE_PTS=true also emits packed float4 (x,y,z,|p|^2) + original ids.
// ---------------------------------------------------------------------------
template <int NPTS, bool WRITE_PTS>
__global__ void __launch_bounds__(512) build_grid(
    const float* __restrict__ p,
    int* __restrict__ cellstart_out,      // [B][NCELL+1] flattened
    unsigned short* __restrict__ id_out)  // [B][NPTS]
{
    __shared__ int counts[NCELL];
    __shared__ int s1[NCELL];
    __shared__ int s2[NCELL];

    const int b = blockIdx.x;
    const int t = threadIdx.x;
    const float* pb = p + (size_t)b * NPTS * 3;

    counts[t] = 0;
    __syncthreads();

    for (int j = t; j < NPTS; j += 512) {
        const float px = pb[j * 3 + 0];
        const float py = pb[j * 3 + 1];
        const float pz = pb[j * 3 + 2];
        const int cx = min(G - 1, (int)(px * (float)G));
        const int cy = min(G - 1, (int)(py * (float)G));
        const int cz = min(G - 1, (int)(pz * (float)G));
        atomicAdd(&counts[cx | (cy << 3) | (cz << 6)], 1);
    }
    __syncthreads();

    // inclusive scan (Hillis-Steele, ping-pong) over 512 cells
    s1[t] = counts[t];
    __syncthreads();
    int* src = s1;
    int* dst = s2;
    for (int d = 1; d < NCELL; d <<= 1) {
        int v = src[t];
        if (t >= d) v += src[t - d];
        dst[t] = v;
        __syncthreads();
        int* tmp = src; src = dst; dst = tmp;
    }
    const int excl = src[t] - counts[t];
    cellstart_out[b * (NCELL + 1) + t] = excl;
    if (t == 0) cellstart_out[b * (NCELL + 1) + NCELL] = NPTS;
    counts[t] = excl;   // scatter cursor
    __syncthreads();

    for (int j = t; j < NPTS; j += 512) {
        const float px = pb[j * 3 + 0];
        const float py = pb[j * 3 + 1];
        const float pz = pb[j * 3 + 2];
        const int cx = min(G - 1, (int)(px * (float)G));
        const int cy = min(G - 1, (int)(py * (float)G));
        const int cz = min(G - 1, (int)(pz * (float)G));
        const int slot = atomicAdd(&counts[cx | (cy << 3) | (cz << 6)], 1);
        id_out[b * NPTS + slot] = (unsigned short)j;
        if (WRITE_PTS) {
            // |p|^2 exactly as reference: (x*x + y*y) + z*z, no fma contraction
            const float pp = __fadd_rn(__fadd_rn(__fmul_rn(px, px), __fmul_rn(py, py)),
                                       __fmul_rn(pz, pz));
            g_pts[b][slot] = make_float4(px, py, pz, pp);
        }
    }
}

// ---------------------------------------------------------------------------
// kNN: one WARP per query cell -> all lanes share an identical candidate cell
// list, so every shared-memory candidate read is a uniform broadcast.
// Distance numerics match the reference gram trick exactly:
//   d2 = (qq + pp) - 2*dot   (dot = fma chain)
// Lexicographic (d2, original index) tie-break == stable jax top_k.
// ---------------------------------------------------------------------------
#define SMEM_Q (N_DOWN * 16 + N_DOWN * 2 + (NCELL + 1) * 4 * 2)

__global__ void __launch_bounds__(256) knn_query(const float* __restrict__ p_up)
{
    extern __shared__ char sm[];
    float4*         spts = (float4*)sm;                                   // 64 KB
    unsigned short* sid  = (unsigned short*)(sm + N_DOWN * 16);           // 8 KB
    int*            scs  = (int*)(sm + N_DOWN * 16 + N_DOWN * 2);         // cellstart
    int*            sqs  = scs + (NCELL + 1);                             // qcellstart

    const int b = blockIdx.y;
    for (int i = threadIdx.x; i < N_DOWN; i += 256) spts[i] = g_pts[b][i];
    for (int i = threadIdx.x; i < N_DOWN; i += 256) sid[i] = g_ptid[b][i];
    for (int i = threadIdx.x; i <= NCELL; i += 256) scs[i] = g_cellstart[b][i];
    for (int i = threadIdx.x; i <= NCELL; i += 256) sqs[i] = g_qcellstart[b][i];
    __syncthreads();

    const int warp = threadIdx.x >> 5;
    const int lane = threadIdx.x & 31;
    const int cell = blockIdx.x * 8 + warp;            // this warp's query cell
    const int cx = cell & 7, cy = (cell >> 3) & 7, cz = cell >> 6;

    const int qs = sqs[cell];
    const int qe = sqs[cell + 1];

    for (int q0 = qs; q0 < qe; q0 += 32) {
        const int  ql     = q0 + lane;
        const bool active = (ql < qe);
        const int  qid    = (int)g_qid[b][active ? ql : qs];
        const int  r      = b * N_UP + qid;

        const float qx = p_up[(size_t)r * 3 + 0];
        const float qy = p_up[(size_t)r * 3 + 1];
        const float qz = p_up[(size_t)r * 3 + 2];
        const float qq = __fadd_rn(__fadd_rn(__fmul_rn(qx, qx), __fmul_rn(qy, qy)),
                                   __fmul_rn(qz, qz));

        float bd0 = 1e30f, bd1 = 1e30f, bd2 = 1e30f, bd3 = active ? 1e30f : -1e30f;
        int   oi0 = 0x7fffffff, oi1 = 0x7fffffff, oi2 = 0x7fffffff, oi3 = 0x7fffffff;

        #define SCAN_CELL(c)                                                        \
        {                                                                           \
            const int e_ = scs[(c) + 1];                                            \
            for (int k_ = scs[(c)]; k_ < e_; k_++) {                                \
                const float4 p_ = spts[k_];                                         \
                float dot_ = __fmul_rn(qx, p_.x);                                   \
                dot_ = fmaf(qy, p_.y, dot_);                                        \
                dot_ = fmaf(qz, p_.z, dot_);                                        \
                const float d2_ = __fadd_rn(__fadd_rn(qq, p_.w),                    \
                                            -__fmul_rn(2.0f, dot_));                \
                const int oid_ = (int)sid[k_];                                      \
                if (d2_ < bd3 || (d2_ == bd3 && oid_ < oi3)) {                      \
                    if (d2_ < bd2 || (d2_ == bd2 && oid_ < oi2)) {                  \
                        bd3 = bd2; oi3 = oi2;                                       \
                        if (d2_ < bd1 || (d2_ == bd1 && oid_ < oi1)) {              \
                            bd2 = bd1; oi2 = oi1;                                   \
                            if (d2_ < bd0 || (d2_ == bd0 && oid_ < oi0)) {          \
                                bd1 = bd0; oi1 = oi0;                               \
                                bd0 = d2_; oi0 = oid_;                              \
                            } else { bd1 = d2_; oi1 = oid_; }                       \
                        } else { bd2 = d2_; oi2 = oid_; }                           \
                    } else { bd3 = d2_; oi3 = oid_; }                               \
                }                                                                   \
            }                                                                       \
        }

        // Chebyshev <= 1 cube (warp-uniform: same cell for all lanes)
        {
            const int z0 = max(0, cz - 1), z1 = min(G - 1, cz + 1);
            const int y0 = max(0, cy - 1), y1 = min(G - 1, cy + 1);
            const int x0 = max(0, cx - 1), x1 = min(G - 1, cx + 1);
            for (int z = z0; z <= z1; z++)
                for (int y = y0; y <= y1; y++)
                    for (int x = x0; x <= x1; x++)
                        SCAN_CELL(x | (y << 3) | (z << 6));
        }

        // expanding shells; exact stop bound: unprocessed cells at Chebyshev
        // >= rad are at distance >= (rad-1)*GH. Warp-vote on exit.
        for (int rad = 2; rad < G; rad++) {
            const float dmin = (float)(rad - 1) * GH;
            if (__all_sync(0xffffffffu, bd3 <= dmin * dmin)) break;
            const int z0 = max(0, cz - rad), z1 = min(G - 1, cz + rad);
            const int y0 = max(0, cy - rad), y1 = min(G - 1, cy + rad);
            const int x0 = max(0, cx - rad), x1 = min(G - 1, cx + rad);
            for (int z = z0; z <= z1; z++) {
                const int az = abs(z - cz);
                for (int y = y0; y <= y1; y++) {
                    const int ay = abs(y - cy);
                    for (int x = x0; x <= x1; x++) {
                        const int ax = abs(x - cx);
                        if (max(ax, max(ay, az)) == rad)
                            SCAN_CELL(x | (y << 3) | (z << 6));
                    }
                }
            }
        }
        #undef SCAN_CELL

        if (active) {
            const float w0 = 1.0f / fmaxf(bd0, 1e-16f);
            const float w1 = 1.0f / fmaxf(bd1, 1e-16f);
            const float w2 = 1.0f / fmaxf(bd2, 1e-16f);
            const float w3 = 1.0f / fmaxf(bd3, 1e-16f);
            const float inv = 1.0f / (((w0 + w1) + w2) + w3);
            g_knn_idx[r * 4 + 0] = oi0;
            g_knn_idx[r * 4 + 1] = oi1;
            g_knn_idx[r * 4 + 2] = oi2;
            g_knn_idx[r * 4 + 3] = oi3;
            g_knn_w[r * 4 + 0] = w0 * inv;
            g_knn_w[r * 4 + 1] = w1 * inv;
            g_knn_w[r * 4 + 2] = w2 * inv;
            g_knn_w[r * 4 + 3] = w3 * inv;
        }
    }
}

// ---------------------------------------------------------------------------
// Register-tiled fp32 GEMM + BN + ReLU. 128x128 tile, BK=16, 256 thr, 8x8/thr.
// ---------------------------------------------------------------------------
#define BM 128
#define BN 128
#define BK 16
#define TM 8
#define TN 8

template <bool FUSED>
__global__ void __launch_bounds__(256, 2) gemm_bn_relu_kernel(
    const float* __restrict__ A,
    const float* __restrict__ W,
    const float* __restrict__ bias,
    const float* __restrict__ gamma,
    const float* __restrict__ beta,
    const float* __restrict__ mean,
    const float* __restrict__ var,
    float* __restrict__ out,
    int Kdim)
{
    __shared__ float As[BK][BM];
    __shared__ float Bs[BK][BN];

    const int tid  = threadIdx.x;
    const int tx   = tid & 15;
    const int ty   = tid >> 4;
    const int row0 = blockIdx.x * BM;

    float acc[TM][TN];
    #pragma unroll
    for (int i = 0; i < TM; i++)
        #pragma unroll
        for (int j = 0; j < TN; j++) acc[i][j] = 0.0f;

    for (int kt = 0; kt < Kdim; kt += BK) {
        #pragma unroll
        for (int i = 0; i < 2; i++) {
            const int f  = tid + i * 256;
            const int rr = f >> 2;
            const int kq = (f & 3) * 4;
            const float4 av = *(const float4*)(A + (size_t)(row0 + rr) * Kdim + kt + kq);
            As[kq + 0][rr] = av.x;
            As[kq + 1][rr] = av.y;
            As[kq + 2][rr] = av.z;
            As[kq + 3][rr] = av.w;
        }
        #pragma unroll
        for (int i = 0; i < 2; i++) {
            const int f  = tid + i * 256;
            const int kr = f >> 5;
            const int cc = (f & 31) * 4;
            *(float4*)&Bs[kr][cc] = *(const float4*)(W + (size_t)(kt + kr) * BN + cc);
        }
        __syncthreads();

        #pragma unroll
        for (int k = 0; k < BK; k++) {
            float a[TM], bb[TN];
            const float4 a0 = *(const float4*)&As[k][ty * TM];
            const float4 a1 = *(const float4*)&As[k][ty * TM + 4];
            a[0] = a0.x; a[1] = a0.y; a[2] = a0.z; a[3] = a0.w;
            a[4] = a1.x; a[5] = a1.y; a[6] = a1.z; a[7] = a1.w;
            const float4 b0 = *(const float4*)&Bs[k][tx * TN];
            const float4 b1 = *(const float4*)&Bs[k][tx * TN + 4];
            bb[0] = b0.x; bb[1] = b0.y; bb[2] = b0.z; bb[3] = b0.w;
            bb[4] = b1.x; bb[5] = b1.y; bb[6] = b1.z; bb[7] = b1.w;
            #pragma unroll
            for (int i = 0; i < TM; i++)
                #pragma unroll
                for (int j = 0; j < TN; j++)
                    acc[i][j] = fmaf(a[i], bb[j], acc[i][j]);
        }
        __syncthreads();
    }

    float scale[TN], shift[TN];
    #pragma unroll
    for (int j = 0; j < TN; j++) {
        const int c = tx * TN + j;
        const float s = gamma[c] * rsqrtf(var[c] + 1e-5f);
        scale[j] = s;
        shift[j] = beta[c] + (bias[c] - mean[c]) * s;
    }

    #pragma unroll
    for (int i = 0; i < TM; i++) {
        const int r = row0 + ty * TM + i;
        float interp[TN];
        #pragma unroll
        for (int j = 0; j < TN; j++) interp[j] = 0.0f;

        if (FUSED) {
            const int bidx = r >> 14;                  // r / N_UP
            const float* xdb = g_xd + (size_t)bidx * N_DOWN * C_OUT;
            #pragma unroll
            for (int k = 0; k < KNN; k++) {
                const int   id = g_knn_idx[r * 4 + k];
                const float wk = g_knn_w[r * 4 + k];
                const float* frow = xdb + (size_t)id * C_OUT + tx * TN;
                #pragma unroll
                for (int j = 0; j < TN; j++)
                    interp[j] = fmaf(wk, frow[j], interp[j]);
            }
        }

        float* dst = FUSED ? out : g_xd;
        float res[TN];
        #pragma unroll
        for (int j = 0; j < TN; j++) {
            float z = fmaf(acc[i][j], scale[j], shift[j]);
            z = fmaxf(z, 0.0f);
            res[j] = z + interp[j];
        }
        *(float4*)(dst + (size_t)r * C_OUT + tx * TN)     = make_float4(res[0], res[1], res[2], res[3]);
        *(float4*)(dst + (size_t)r * C_OUT + tx * TN + 4) = make_float4(res[4], res[5], res[6], res[7]);
    }
}

// ---------------------------------------------------------------------------
// Launch
// ---------------------------------------------------------------------------
extern "C" void kernel_launch(void* const* d_in, const int* in_sizes, int n_in,
                              void* d_out, int out_size)
{
    const float* x_down  = (const float*)d_in[0];
    const float* x_up    = (const float*)d_in[1];
    const float* p_down  = (const float*)d_in[2];
    const float* p_up    = (const float*)d_in[3];
    const float* W_down  = (const float*)d_in[4];
    const float* b_down  = (const float*)d_in[5];
    const float* g_down  = (const float*)d_in[6];
    const float* be_down = (const float*)d_in[7];
    const float* m_down  = (const float*)d_in[8];
    const float* v_down  = (const float*)d_in[9];
    const float* W_up    = (const float*)d_in[10];
    const float* b_up    = (const float*)d_in[11];
    const float* g_up    = (const float*)d_in[12];
    const float* be_up   = (const float*)d_in[13];
    const float* m_up    = (const float*)d_in[14];
    const float* v_up    = (const float*)d_in[15];
    float* out = (float*)d_out;

    cudaFuncSetAttribute(knn_query, cudaFuncAttributeMaxDynamicSharedMemorySize, SMEM_Q);

    int* cs;  cudaGetSymbolAddress((void**)&cs, g_cellstart);
    int* qcs; cudaGetSymbolAddress((void**)&qcs, g_qcellstart);
    unsigned short* pid; cudaGetSymbolAddress((void**)&pid, g_ptid);
    unsigned short* qid; cudaGetSymbolAddress((void**)&qid, g_qid);

    // 1) grids for points and queries
    build_grid<N_DOWN, true ><<<B_SZ, 512>>>(p_down, cs,  pid);
    build_grid<N_UP,   false><<<B_SZ, 512>>>(p_up,   qcs, qid);

    // 2) warp-per-cell kNN
    dim3 qgrid(NCELL / 8, B_SZ);
    knn_query<<<qgrid, 256, SMEM_Q>>>(p_up);

    // 3) down MLP -> g_xd   (M=16384, K=256)
    gemm_bn_relu_kernel<false><<<M_DOWN / BM, 256>>>(
        x_down, W_down, b_down, g_down, be_down, m_down, v_down,
        nullptr, C_IN);

    // 4) up MLP + gather + add -> out   (M=65536, K=128)
    gemm_bn_relu_kernel<true><<<M_UP / BM, 256>>>(
        x_up, W_up, b_up, g_up, be_up, m_up, v_up,
        out, C_OUT);
}

// round 6
// speedup vs baseline: 1.7315x; 1.2685x over previous
#include <cuda_runtime.h>
#include <cuda_bf16.h>
#include <cstdint>

// ---------------------------------------------------------------------------
// Problem shape (fixed)
// ---------------------------------------------------------------------------
#define B_SZ   4
#define N_DOWN 4096
#define N_UP   16384
#define C_IN   256
#define C_OUT  128
#define KNN    4

#define M_DOWN (B_SZ * N_DOWN)   // 16384
#define M_UP   (B_SZ * N_UP)     // 65536

// Spatial grid: 8x8x8 over [0,1]^3
#define G      8
#define NCELL  (G * G * G)
#define GH     0.125f

// ---------------------------------------------------------------------------
// Helpers
// ---------------------------------------------------------------------------
__device__ __forceinline__ uint32_t smem_u32(const void* p) {
    uint32_t a;
    asm("{ .reg .u64 t; cvta.to.shared.u64 t, %1; cvt.u32.u64 %0, t; }" : "=r"(a) : "l"(p));
    return a;
}

#define LDSM_X4(r0, r1, r2, r3, addr)                                             \
    asm volatile("ldmatrix.sync.aligned.m8n8.x4.shared.b16 {%0,%1,%2,%3}, [%4];"  \
                 : "=r"(r0), "=r"(r1), "=r"(r2), "=r"(r3) : "r"(addr))

__device__ __forceinline__ void mma_bf16(float* c, const uint32_t* a,
                                         uint32_t b0, uint32_t b1) {
    asm volatile(
        "mma.sync.aligned.m16n8k16.row.col.f32.bf16.bf16.f32 "
        "{%0,%1,%2,%3}, {%4,%5,%6,%7}, {%8,%9}, {%0,%1,%2,%3};"
        : "+f"(c[0]), "+f"(c[1]), "+f"(c[2]), "+f"(c[3])
        : "r"(a[0]), "r"(a[1]), "r"(a[2]), "r"(a[3]), "r"(b0), "r"(b1));
}

// ---------------------------------------------------------------------------
// Device-global scratch
// ---------------------------------------------------------------------------
__device__ float g_xd[M_DOWN * C_OUT];              // 8 MB
__device__ int   g_knn_idx[M_UP * KNN];
__device__ float g_knn_w[M_UP * KNN];
__device__ float4         g_pts[B_SZ][N_DOWN];
__device__ unsigned short g_ptid[B_SZ][N_DOWN];
__device__ int            g_cellstart[B_SZ][NCELL + 1];
__device__ unsigned short g_qid[B_SZ][N_UP];
__device__ int            g_qcellstart[B_SZ][NCELL + 1];
// Pre-split, pre-transposed weights: [N][K] K-major bf16 (matches mma .col B)
__device__ __nv_bfloat16 g_Wd_hi[C_OUT * C_IN];
__device__ __nv_bfloat16 g_Wd_lo[C_OUT * C_IN];
__device__ __nv_bfloat16 g_Wu_hi[C_OUT * C_OUT];
__device__ __nv_bfloat16 g_Wu_lo[C_OUT * C_OUT];

// ---------------------------------------------------------------------------
// Weight prep: transpose + hi/lo bf16 split
// ---------------------------------------------------------------------------
__global__ void __launch_bounds__(256) prep_weights(const float* __restrict__ W_down,
                                                    const float* __restrict__ W_up)
{
    const int idx = blockIdx.x * 256 + threadIdx.x;
    if (idx < C_OUT * C_IN) {
        const int n = idx >> 8;
        const int k = idx & 255;
        const float v = W_down[k * C_OUT + n];
        const __nv_bfloat16 h = __float2bfloat16(v);
        g_Wd_hi[n * C_IN + k] = h;
        g_Wd_lo[n * C_IN + k] = __float2bfloat16(v - __bfloat162float(h));
    } else {
        const int j = idx - C_OUT * C_IN;
        if (j < C_OUT * C_OUT) {
            const int n = j >> 7;
            const int k = j & 127;
            const float v = W_up[k * C_OUT + n];
            const __nv_bfloat16 h = __float2bfloat16(v);
            g_Wu_hi[n * C_OUT + k] = h;
            g_Wu_lo[n * C_OUT + k] = __float2bfloat16(v - __bfloat162float(h));
        }
    }
}

// ---------------------------------------------------------------------------
// Grid build (unchanged from R4)
// ---------------------------------------------------------------------------
template <int NPTS, bool WRITE_PTS>
__global__ void __launch_bounds__(512) build_grid(
    const float* __restrict__ p,
    int* __restrict__ cellstart_out,
    unsigned short* __restrict__ id_out)
{
    __shared__ int counts[NCELL];
    __shared__ int s1[NCELL];
    __shared__ int s2[NCELL];

    const int b = blockIdx.x;
    const int t = threadIdx.x;
    const float* pb = p + (size_t)b * NPTS * 3;

    counts[t] = 0;
    __syncthreads();

    for (int j = t; j < NPTS; j += 512) {
        const float px = pb[j * 3 + 0];
        const float py = pb[j * 3 + 1];
        const float pz = pb[j * 3 + 2];
        const int cx = min(G - 1, (int)(px * (float)G));
        const int cy = min(G - 1, (int)(py * (float)G));
        const int cz = min(G - 1, (int)(pz * (float)G));
        atomicAdd(&counts[cx | (cy << 3) | (cz << 6)], 1);
    }
    __syncthreads();

    s1[t] = counts[t];
    __syncthreads();
    int* src = s1;
    int* dst = s2;
    for (int d = 1; d < NCELL; d <<= 1) {
        int v = src[t];
        if (t >= d) v += src[t - d];
        dst[t] = v;
        __syncthreads();
        int* tmp = src; src = dst; dst = tmp;
    }
    const int excl = src[t] - counts[t];
    cellstart_out[b * (NCELL + 1) + t] = excl;
    if (t == 0) cellstart_out[b * (NCELL + 1) + NCELL] = NPTS;
    counts[t] = excl;
    __syncthreads();

    for (int j = t; j < NPTS; j += 512) {
        const float px = pb[j * 3 + 0];
        const float py = pb[j * 3 + 1];
        const float pz = pb[j * 3 + 2];
        const int cx = min(G - 1, (int)(px * (float)G));
        const int cy = min(G - 1, (int)(py * (float)G));
        const int cz = min(G - 1, (int)(pz * (float)G));
        const int slot = atomicAdd(&counts[cx | (cy << 3) | (cz << 6)], 1);
        id_out[b * NPTS + slot] = (unsigned short)j;
        if (WRITE_PTS) {
            const float pp = __fadd_rn(__fadd_rn(__fmul_rn(px, px), __fmul_rn(py, py)),
                                       __fmul_rn(pz, pz));
            g_pts[b][slot] = make_float4(px, py, pz, pp);
        }
    }
}

// ---------------------------------------------------------------------------
// kNN (unchanged from R4): warp per query cell, gram-trick numerics,
// lexicographic (d2, original index) tie-break == stable jax top_k.
// ---------------------------------------------------------------------------
#define SMEM_Q (N_DOWN * 16 + N_DOWN * 2 + (NCELL + 1) * 4 * 2)

__global__ void __launch_bounds__(256) knn_query(const float* __restrict__ p_up)
{
    extern __shared__ char sm[];
    float4*         spts = (float4*)sm;
    unsigned short* sid  = (unsigned short*)(sm + N_DOWN * 16);
    int*            scs  = (int*)(sm + N_DOWN * 16 + N_DOWN * 2);
    int*            sqs  = scs + (NCELL + 1);

    const int b = blockIdx.y;
    for (int i = threadIdx.x; i < N_DOWN; i += 256) spts[i] = g_pts[b][i];
    for (int i = threadIdx.x; i < N_DOWN; i += 256) sid[i] = g_ptid[b][i];
    for (int i = threadIdx.x; i <= NCELL; i += 256) scs[i] = g_cellstart[b][i];
    for (int i = threadIdx.x; i <= NCELL; i += 256) sqs[i] = g_qcellstart[b][i];
    __syncthreads();

    const int warp = threadIdx.x >> 5;
    const int lane = threadIdx.x & 31;
    const int cell = blockIdx.x * 8 + warp;
    const int cx = cell & 7, cy = (cell >> 3) & 7, cz = cell >> 6;

    const int qs = sqs[cell];
    const int qe = sqs[cell + 1];

    for (int q0 = qs; q0 < qe; q0 += 32) {
        const int  ql     = q0 + lane;
        const bool active = (ql < qe);
        const int  qid    = (int)g_qid[b][active ? ql : qs];
        const int  r      = b * N_UP + qid;

        const float qx = p_up[(size_t)r * 3 + 0];
        const float qy = p_up[(size_t)r * 3 + 1];
        const float qz = p_up[(size_t)r * 3 + 2];
        const float qq = __fadd_rn(__fadd_rn(__fmul_rn(qx, qx), __fmul_rn(qy, qy)),
                                   __fmul_rn(qz, qz));

        float bd0 = 1e30f, bd1 = 1e30f, bd2 = 1e30f, bd3 = active ? 1e30f : -1e30f;
        int   oi0 = 0x7fffffff, oi1 = 0x7fffffff, oi2 = 0x7fffffff, oi3 = 0x7fffffff;

        #define SCAN_CELL(c)                                                        \
        {                                                                           \
            const int e_ = scs[(c) + 1];                                            \
            for (int k_ = scs[(c)]; k_ < e_; k_++) {                                \
                const float4 p_ = spts[k_];                                         \
                float dot_ = __fmul_rn(qx, p_.x);                                   \
                dot_ = fmaf(qy, p_.y, dot_);                                        \
                dot_ = fmaf(qz, p_.z, dot_);                                        \
                const float d2_ = __fadd_rn(__fadd_rn(qq, p_.w),                    \
                                            -__fmul_rn(2.0f, dot_));                \
                const int oid_ = (int)sid[k_];                                      \
                if (d2_ < bd3 || (d2_ == bd3 && oid_ < oi3)) {                      \
                    if (d2_ < bd2 || (d2_ == bd2 && oid_ < oi2)) {                  \
                        bd3 = bd2; oi3 = oi2;                                       \
                        if (d2_ < bd1 || (d2_ == bd1 && oid_ < oi1)) {              \
                            bd2 = bd1; oi2 = oi1;                                   \
                            if (d2_ < bd0 || (d2_ == bd0 && oid_ < oi0)) {          \
                                bd1 = bd0; oi1 = oi0;                               \
                                bd0 = d2_; oi0 = oid_;                              \
                            } else { bd1 = d2_; oi1 = oid_; }                       \
                        } else { bd2 = d2_; oi2 = oid_; }                           \
                    } else { bd3 = d2_; oi3 = oid_; }                               \
                }                                                                   \
            }                                                                       \
        }

        {
            const int z0 = max(0, cz - 1), z1 = min(G - 1, cz + 1);
            const int y0 = max(0, cy - 1), y1 = min(G - 1, cy + 1);
            const int x0 = max(0, cx - 1), x1 = min(G - 1, cx + 1);
            for (int z = z0; z <= z1; z++)
                for (int y = y0; y <= y1; y++)
                    for (int x = x0; x <= x1; x++)
                        SCAN_CELL(x | (y << 3) | (z << 6));
        }

        for (int rad = 2; rad < G; rad++) {
            const float dmin = (float)(rad - 1) * GH;
            if (__all_sync(0xffffffffu, bd3 <= dmin * dmin)) break;
            const int z0 = max(0, cz - rad), z1 = min(G - 1, cz + rad);
            const int y0 = max(0, cy - rad), y1 = min(G - 1, cy + rad);
            const int x0 = max(0, cx - rad), x1 = min(G - 1, cx + rad);
            for (int z = z0; z <= z1; z++) {
                const int az = abs(z - cz);
                for (int y = y0; y <= y1; y++) {
                    const int ay = abs(y - cy);
                    for (int x = x0; x <= x1; x++) {
                        const int ax = abs(x - cx);
                        if (max(ax, max(ay, az)) == rad)
                            SCAN_CELL(x | (y << 3) | (z << 6));
                    }
                }
            }
        }
        #undef SCAN_CELL

        if (active) {
            const float w0 = 1.0f / fmaxf(bd0, 1e-16f);
            const float w1 = 1.0f / fmaxf(bd1, 1e-16f);
            const float w2 = 1.0f / fmaxf(bd2, 1e-16f);
            const float w3 = 1.0f / fmaxf(bd3, 1e-16f);
            const float inv = 1.0f / (((w0 + w1) + w2) + w3);
            g_knn_idx[r * 4 + 0] = oi0;
            g_knn_idx[r * 4 + 1] = oi1;
            g_knn_idx[r * 4 + 2] = oi2;
            g_knn_idx[r * 4 + 3] = oi3;
            g_knn_w[r * 4 + 0] = w0 * inv;
            g_knn_w[r * 4 + 1] = w1 * inv;
            g_knn_w[r * 4 + 2] = w2 * inv;
            g_knn_w[r * 4 + 3] = w3 * inv;
        }
    }
}

// ---------------------------------------------------------------------------
// Tensor-core GEMM (mma.sync bf16, hi/lo split) + BN + ReLU (+ gather/add).
// CTA: 128x128, 8 warps (warp tile 32m x 64n), BK=32.
// A fp32 -> hi/lo bf16 converted on the fly; W pre-split [N][K] bf16.
// 3 MMAs per k-step: Ahi*Whi + Ahi*Wlo + Alo*Whi (fp32-faithful).
// Smem rows padded to 80 B -> ldmatrix conflict-free (20*i mod 32 distinct).
// ---------------------------------------------------------------------------
#define ROWB 80   // smem row pitch in bytes (32 bf16 = 64 B data + 16 B pad)

template <int KDIM, bool FUSED>
__global__ void __launch_bounds__(256) gemm_mma(
    const float* __restrict__ A,
    const __nv_bfloat16* __restrict__ Whi,
    const __nv_bfloat16* __restrict__ Wlo,
    const float* __restrict__ bias,
    const float* __restrict__ gamma,
    const float* __restrict__ beta,
    const float* __restrict__ mean,
    const float* __restrict__ var,
    float* __restrict__ outp)
{
    __shared__ __align__(16) uint8_t sAh[128 * ROWB];
    __shared__ __align__(16) uint8_t sAl[128 * ROWB];
    __shared__ __align__(16) uint8_t sBh[128 * ROWB];
    __shared__ __align__(16) uint8_t sBl[128 * ROWB];
    __shared__ float scale_s[C_OUT];
    __shared__ float shift_s[C_OUT];

    const int tid  = threadIdx.x;
    const int wid  = tid >> 5;
    const int lane = tid & 31;
    const int wm   = wid & 3;          // warp row group (32 rows)
    const int wn   = wid >> 2;         // warp col group (64 cols)
    const int row0 = blockIdx.x * 128;

    if (tid < C_OUT) {
        const float s = gamma[tid] * rsqrtf(var[tid] + 1e-5f);
        scale_s[tid] = s;
        shift_s[tid] = beta[tid] + (bias[tid] - mean[tid]) * s;
    }

    float acc[2][8][4];
    #pragma unroll
    for (int mt = 0; mt < 2; mt++)
        #pragma unroll
        for (int nt = 0; nt < 8; nt++)
            #pragma unroll
            for (int c = 0; c < 4; c++) acc[mt][nt][c] = 0.0f;

    // per-lane ldmatrix address components
    const uint32_t sAh_b = smem_u32(sAh), sAl_b = smem_u32(sAl);
    const uint32_t sBh_b = smem_u32(sBh), sBl_b = smem_u32(sBl);
    const int a_row  = wm * 32 + (lane & 7) + ((lane >> 3) & 1) * 8;
    const int a_kby  = ((lane >> 4) & 1) * 16;                       // bytes
    const int b_nrow = wn * 64 + (lane & 7) + ((lane >> 4) & 1) * 8;
    const int b_kby  = ((lane >> 3) & 1) * 16;

    // gmem staging mapping: 2 threads per row
    const int rr   = tid >> 1;          // 0..127
    const int half = tid & 1;           // k halves of 16

    for (int kc = 0; kc < KDIM / 32; kc++) {
        const int kt = kc * 32;

        // ---- A: 128 x 32 fp32 -> hi/lo bf16 ----
        {
            const float* ap = A + (size_t)(row0 + rr) * KDIM + kt + half * 16;
            const uint32_t wb = rr * ROWB + half * 32;
            #pragma unroll
            for (int q = 0; q < 2; q++) {
                const float4 v0 = *(const float4*)(ap + q * 8);
                const float4 v1 = *(const float4*)(ap + q * 8 + 4);
                __nv_bfloat162 h0 = __floats2bfloat162_rn(v0.x, v0.y);
                __nv_bfloat162 h1 = __floats2bfloat162_rn(v0.z, v0.w);
                __nv_bfloat162 h2 = __floats2bfloat162_rn(v1.x, v1.y);
                __nv_bfloat162 h3 = __floats2bfloat162_rn(v1.z, v1.w);
                __nv_bfloat162 l0 = __floats2bfloat162_rn(v0.x - __bfloat162float(h0.x),
                                                          v0.y - __bfloat162float(h0.y));
                __nv_bfloat162 l1 = __floats2bfloat162_rn(v0.z - __bfloat162float(h1.x),
                                                          v0.w - __bfloat162float(h1.y));
                __nv_bfloat162 l2 = __floats2bfloat162_rn(v1.x - __bfloat162float(h2.x),
                                                          v1.y - __bfloat162float(h2.y));
                __nv_bfloat162 l3 = __floats2bfloat162_rn(v1.z - __bfloat162float(h3.x),
                                                          v1.w - __bfloat162float(h3.y));
                *(uint4*)(sAh + wb + q * 16) = make_uint4(
                    *(uint32_t*)&h0, *(uint32_t*)&h1, *(uint32_t*)&h2, *(uint32_t*)&h3);
                *(uint4*)(sAl + wb + q * 16) = make_uint4(
                    *(uint32_t*)&l0, *(uint32_t*)&l1, *(uint32_t*)&l2, *(uint32_t*)&l3);
            }
        }
        // ---- W: 128 x 32 bf16 hi/lo ----
        {
            const __nv_bfloat16* wh = Whi + (size_t)rr * KDIM + kt + half * 16;
            const __nv_bfloat16* wl = Wlo + (size_t)rr * KDIM + kt + half * 16;
            const uint32_t wb = rr * ROWB + half * 32;
            *(uint4*)(sBh + wb)      = *(const uint4*)(wh);
            *(uint4*)(sBh + wb + 16) = *(const uint4*)(wh + 8);
            *(uint4*)(sBl + wb)      = *(const uint4*)(wl);
            *(uint4*)(sBl + wb + 16) = *(const uint4*)(wl + 8);
        }
        __syncthreads();

        #pragma unroll
        for (int kk = 0; kk < 32; kk += 16) {
            uint32_t ah[2][4], al[2][4];
            #pragma unroll
            for (int mt = 0; mt < 2; mt++) {
                const uint32_t ao = (uint32_t)((a_row + mt * 16) * ROWB + kk * 2 + a_kby);
                LDSM_X4(ah[mt][0], ah[mt][1], ah[mt][2], ah[mt][3], sAh_b + ao);
                LDSM_X4(al[mt][0], al[mt][1], al[mt][2], al[mt][3], sAl_b + ao);
            }
            #pragma unroll
            for (int ntp = 0; ntp < 4; ntp++) {
                const uint32_t bo = (uint32_t)((b_nrow + ntp * 16) * ROWB + kk * 2 + b_kby);
                uint32_t bh0, bh1, bh2, bh3, bl0, bl1, bl2, bl3;
                LDSM_X4(bh0, bh1, bh2, bh3, sBh_b + bo);
                LDSM_X4(bl0, bl1, bl2, bl3, sBl_b + bo);
                #pragma unroll
                for (int mt = 0; mt < 2; mt++) {
                    mma_bf16(acc[mt][ntp * 2 + 0], ah[mt], bh0, bh1);
                    mma_bf16(acc[mt][ntp * 2 + 0], al[mt], bh0, bh1);
                    mma_bf16(acc[mt][ntp * 2 + 1], ah[mt], bh2, bh3);
                    mma_bf16(acc[mt][ntp * 2 + 1], al[mt], bh2, bh3);
                    mma_bf16(acc[mt][ntp * 2 + 0], ah[mt], bl0, bl1);
                    mma_bf16(acc[mt][ntp * 2 + 1], ah[mt], bl2, bl3);
                }
            }
        }
        __syncthreads();
    }

    // ---- Epilogue ----
    float* dst = FUSED ? outp : g_xd;
    const int quad = lane >> 2;
    const int tq2  = (lane & 3) * 2;

    #pragma unroll
    for (int mt = 0; mt < 2; mt++) {
        #pragma unroll
        for (int h = 0; h < 2; h++) {
            const int r = row0 + wm * 32 + mt * 16 + quad + h * 8;

            const float* fr[KNN];
            float wk[KNN];
            if (FUSED) {
                const int bidx = r >> 14;
                const float* xdb = g_xd + (size_t)bidx * N_DOWN * C_OUT;
                #pragma unroll
                for (int k = 0; k < KNN; k++) {
                    fr[k] = xdb + (size_t)g_knn_idx[r * 4 + k] * C_OUT;
                    wk[k] = g_knn_w[r * 4 + k];
                }
            }

            #pragma unroll
            for (int nt = 0; nt < 8; nt++) {
                const int col = wn * 64 + nt * 8 + tq2;
                float o0 = fmaxf(fmaf(acc[mt][nt][h * 2 + 0], scale_s[col],     shift_s[col]),     0.0f);
                float o1 = fmaxf(fmaf(acc[mt][nt][h * 2 + 1], scale_s[col + 1], shift_s[col + 1]), 0.0f);
                if (FUSED) {
                    #pragma unroll
                    for (int k = 0; k < KNN; k++) {
                        const float2 v = *(const float2*)(fr[k] + col);
                        o0 = fmaf(wk[k], v.x, o0);
                        o1 = fmaf(wk[k], v.y, o1);
                    }
                }
                *(float2*)(dst + (size_t)r * C_OUT + col) = make_float2(o0, o1);
            }
        }
    }
}

// ---------------------------------------------------------------------------
// Launch
// ---------------------------------------------------------------------------
extern "C" void kernel_launch(void* const* d_in, const int* in_sizes, int n_in,
                              void* d_out, int out_size)
{
    const float* x_down  = (const float*)d_in[0];
    const float* x_up    = (const float*)d_in[1];
    const float* p_down  = (const float*)d_in[2];
    const float* p_up    = (const float*)d_in[3];
    const float* W_down  = (const float*)d_in[4];
    const float* b_down  = (const float*)d_in[5];
    const float* g_down  = (const float*)d_in[6];
    const float* be_down = (const float*)d_in[7];
    const float* m_down  = (const float*)d_in[8];
    const float* v_down  = (const float*)d_in[9];
    const float* W_up    = (const float*)d_in[10];
    const float* b_up    = (const float*)d_in[11];
    const float* g_up    = (const float*)d_in[12];
    const float* be_up   = (const float*)d_in[13];
    const float* m_up    = (const float*)d_in[14];
    const float* v_up    = (const float*)d_in[15];
    float* out = (float*)d_out;

    cudaFuncSetAttribute(knn_query, cudaFuncAttributeMaxDynamicSharedMemorySize, SMEM_Q);

    int* cs;  cudaGetSymbolAddress((void**)&cs, g_cellstart);
    int* qcs; cudaGetSymbolAddress((void**)&qcs, g_qcellstart);
    unsigned short* pid; cudaGetSymbolAddress((void**)&pid, g_ptid);
    unsigned short* qid; cudaGetSymbolAddress((void**)&qid, g_qid);
    __nv_bfloat16 *wdh, *wdl, *wuh, *wul;
    cudaGetSymbolAddress((void**)&wdh, g_Wd_hi);
    cudaGetSymbolAddress((void**)&wdl, g_Wd_lo);
    cudaGetSymbolAddress((void**)&wuh, g_Wu_hi);
    cudaGetSymbolAddress((void**)&wul, g_Wu_lo);

    // 0) weight transpose + split
    prep_weights<<<(C_OUT * C_IN + C_OUT * C_OUT + 255) / 256, 256>>>(W_down, W_up);

    // 1) spatial grids + kNN
    build_grid<N_DOWN, true ><<<B_SZ, 512>>>(p_down, cs,  pid);
    build_grid<N_UP,   false><<<B_SZ, 512>>>(p_up,   qcs, qid);
    dim3 qgrid(NCELL / 8, B_SZ);
    knn_query<<<qgrid, 256, SMEM_Q>>>(p_up);

    // 2) down MLP -> g_xd  (tensor cores, M=16384, K=256)
    gemm_mma<C_IN, false><<<M_DOWN / 128, 256>>>(
        x_down, wdh, wdl, b_down, g_down, be_down, m_down, v_down, nullptr);

    // 3) up MLP + gather + add -> out  (tensor cores, M=65536, K=128)
    gemm_mma<C_OUT, true><<<M_UP / 128, 256>>>(
        x_up, wuh, wul, b_up, g_up, be_up, m_up, v_up, out);
}

// round 7
// speedup vs baseline: 1.7890x; 1.0332x over previous
#include <cuda_runtime.h>
#include <cuda_bf16.h>
#include <cstdint>

// ---------------------------------------------------------------------------
// Problem shape (fixed)
// ---------------------------------------------------------------------------
#define B_SZ   4
#define N_DOWN 4096
#define N_UP   16384
#define C_IN   256
#define C_OUT  128
#define KNN    4

#define M_DOWN (B_SZ * N_DOWN)   // 16384
#define M_UP   (B_SZ * N_UP)     // 65536

// Spatial grid: 8x8x8 over [0,1]^3
#define G      8
#define NCELL  (G * G * G)
#define GH     0.125f

// ---------------------------------------------------------------------------
// Helpers
// ---------------------------------------------------------------------------
__device__ __forceinline__ uint32_t smem_u32(const void* p) {
    uint32_t a;
    asm("{ .reg .u64 t; cvta.to.shared.u64 t, %1; cvt.u32.u64 %0, t; }" : "=r"(a) : "l"(p));
    return a;
}

#define LDSM_X4(r0, r1, r2, r3, addr)                                             \
    asm volatile("ldmatrix.sync.aligned.m8n8.x4.shared.b16 {%0,%1,%2,%3}, [%4];"  \
                 : "=r"(r0), "=r"(r1), "=r"(r2), "=r"(r3) : "r"(addr))

__device__ __forceinline__ void mma_bf16(float* c, const uint32_t* a,
                                         uint32_t b0, uint32_t b1) {
    asm volatile(
        "mma.sync.aligned.m16n8k16.row.col.f32.bf16.bf16.f32 "
        "{%0,%1,%2,%3}, {%4,%5,%6,%7}, {%8,%9}, {%0,%1,%2,%3};"
        : "+f"(c[0]), "+f"(c[1]), "+f"(c[2]), "+f"(c[3])
        : "r"(a[0]), "r"(a[1]), "r"(a[2]), "r"(a[3]), "r"(b0), "r"(b1));
}

// monotone key: flip fp32 bits so unsigned compare == float compare
__device__ __forceinline__ uint32_t flip_f32(float f) {
    const uint32_t fb = __float_as_uint(f);
    return (fb & 0x80000000u) ? ~fb : (fb | 0x80000000u);
}
__device__ __forceinline__ float unflip_f32(uint32_t u) {
    return __uint_as_float((u & 0x80000000u) ? (u ^ 0x80000000u) : ~u);
}

// ---------------------------------------------------------------------------
// Device-global scratch
// ---------------------------------------------------------------------------
__device__ float g_xd[M_DOWN * C_OUT];              // 8 MB
__device__ int   g_knn_idx[M_UP * KNN];
__device__ float g_knn_w[M_UP * KNN];
__device__ float4         g_pts[B_SZ][N_DOWN];      // cell-sorted (x,y,z,|p|^2)
__device__ uint32_t       g_pid32[B_SZ][N_DOWN];    // sorted -> original index
__device__ int            g_cellstart[B_SZ][NCELL + 1];
__device__ unsigned short g_qid[B_SZ][N_UP];        // queries sorted by cell
__device__ int            g_qcellstart[B_SZ][NCELL + 1];
// Pre-split, pre-transposed weights: [N][K] K-major bf16 (matches mma .col B)
__device__ __nv_bfloat16 g_Wd_hi[C_OUT * C_IN];
__device__ __nv_bfloat16 g_Wd_lo[C_OUT * C_IN];
__device__ __nv_bfloat16 g_Wu_hi[C_OUT * C_OUT];
__device__ __nv_bfloat16 g_Wu_lo[C_OUT * C_OUT];

// ---------------------------------------------------------------------------
// Weight prep: transpose + hi/lo bf16 split
// ---------------------------------------------------------------------------
__global__ void __launch_bounds__(256) prep_weights(const float* __restrict__ W_down,
                                                    const float* __restrict__ W_up)
{
    const int idx = blockIdx.x * 256 + threadIdx.x;
    if (idx < C_OUT * C_IN) {
        const int n = idx >> 8;
        const int k = idx & 255;
        const float v = W_down[k * C_OUT + n];
        const __nv_bfloat16 h = __float2bfloat16(v);
        g_Wd_hi[n * C_IN + k] = h;
        g_Wd_lo[n * C_IN + k] = __float2bfloat16(v - __bfloat162float(h));
    } else {
        const int j = idx - C_OUT * C_IN;
        if (j < C_OUT * C_OUT) {
            const int n = j >> 7;
            const int k = j & 127;
            const float v = W_up[k * C_OUT + n];
            const __nv_bfloat16 h = __float2bfloat16(v);
            g_Wu_hi[n * C_OUT + k] = h;
            g_Wu_lo[n * C_OUT + k] = __float2bfloat16(v - __bfloat162float(h));
        }
    }
}

// ---------------------------------------------------------------------------
// Grid build: one block per batch, 512 threads. count -> scan -> scatter.
// ---------------------------------------------------------------------------
template <int NPTS, bool WRITE_PTS>
__global__ void __launch_bounds__(512) build_grid(
    const float* __restrict__ p,
    int* __restrict__ cellstart_out,
    unsigned short* __restrict__ id_out)
{
    __shared__ int counts[NCELL];
    __shared__ int s1[NCELL];
    __shared__ int s2[NCELL];

    const int b = blockIdx.x;
    const int t = threadIdx.x;
    const float* pb = p + (size_t)b * NPTS * 3;

    counts[t] = 0;
    __syncthreads();

    for (int j = t; j < NPTS; j += 512) {
        const float px = pb[j * 3 + 0];
        const float py = pb[j * 3 + 1];
        const float pz = pb[j * 3 + 2];
        const int cx = min(G - 1, (int)(px * (float)G));
        const int cy = min(G - 1, (int)(py * (float)G));
        const int cz = min(G - 1, (int)(pz * (float)G));
        atomicAdd(&counts[cx | (cy << 3) | (cz << 6)], 1);
    }
    __syncthreads();

    s1[t] = counts[t];
    __syncthreads();
    int* src = s1;
    int* dst = s2;
    for (int d = 1; d < NCELL; d <<= 1) {
        int v = src[t];
        if (t >= d) v += src[t - d];
        dst[t] = v;
        __syncthreads();
        int* tmp = src; src = dst; dst = tmp;
    }
    const int excl = src[t] - counts[t];
    cellstart_out[b * (NCELL + 1) + t] = excl;
    if (t == 0) cellstart_out[b * (NCELL + 1) + NCELL] = NPTS;
    counts[t] = excl;
    __syncthreads();

    for (int j = t; j < NPTS; j += 512) {
        const float px = pb[j * 3 + 0];
        const float py = pb[j * 3 + 1];
        const float pz = pb[j * 3 + 2];
        const int cx = min(G - 1, (int)(px * (float)G));
        const int cy = min(G - 1, (int)(py * (float)G));
        const int cz = min(G - 1, (int)(pz * (float)G));
        const int slot = atomicAdd(&counts[cx | (cy << 3) | (cz << 6)], 1);
        if (WRITE_PTS) {
            const float pp = __fadd_rn(__fadd_rn(__fmul_rn(px, px), __fmul_rn(py, py)),
                                       __fmul_rn(pz, pz));
            g_pts[b][slot]  = make_float4(px, py, pz, pp);
            g_pid32[b][slot] = (uint32_t)j;
        } else {
            id_out[b * NPTS + slot] = (unsigned short)j;
        }
    }
}

// ---------------------------------------------------------------------------
// kNN: one WARP per query cell; all lanes share the identical candidate cell
// list, so every candidate load is a warp-uniform broadcast (L1-hot global).
// No shared memory, no barriers -> no occupancy cap.
// Branchless top-4: u64 key = (flip(d2) << 16) | orig_id; a single unsigned
// compare reproduces the exact lexicographic (d2, index) semantics of stable
// jax top_k (-0.0 / NaN provably cannot occur for these inputs).
// Distance numerics match the reference gram trick exactly.
// ---------------------------------------------------------------------------
__global__ void __launch_bounds__(128) knn_query(const float* __restrict__ p_up)
{
    const int b    = blockIdx.y;
    const int warp = threadIdx.x >> 5;
    const int lane = threadIdx.x & 31;
    const int cell = blockIdx.x * 4 + warp;
    const int cx = cell & 7, cy = (cell >> 3) & 7, cz = cell >> 6;

    const float4*   pts = g_pts[b];
    const uint32_t* pid = g_pid32[b];
    const int*      cst = g_cellstart[b];

    const int qs = g_qcellstart[b][cell];
    const int qe = g_qcellstart[b][cell + 1];

    for (int q0 = qs; q0 < qe; q0 += 32) {
        const int  ql     = q0 + lane;
        const bool active = (ql < qe);
        const int  qid    = (int)g_qid[b][active ? ql : qs];  // inactive lanes duplicate qs
        const int  r      = b * N_UP + qid;

        const float qx = __ldg(&p_up[(size_t)r * 3 + 0]);
        const float qy = __ldg(&p_up[(size_t)r * 3 + 1]);
        const float qz = __ldg(&p_up[(size_t)r * 3 + 2]);
        const float qq = __fadd_rn(__fadd_rn(__fmul_rn(qx, qx), __fmul_rn(qy, qy)),
                                   __fmul_rn(qz, qz));

        uint64_t k0 = ~0ull, k1 = ~0ull, k2 = ~0ull, k3 = ~0ull;

        #define SCAN_CELL(c)                                                        \
        {                                                                           \
            const int e_ = __ldg(&cst[(c) + 1]);                                    \
            for (int j_ = __ldg(&cst[(c)]); j_ < e_; j_++) {                        \
                const float4 p_ = __ldg(&pts[j_]);                                  \
                const uint32_t oid_ = __ldg(&pid[j_]);                              \
                float dot_ = __fmul_rn(qx, p_.x);                                   \
                dot_ = fmaf(qy, p_.y, dot_);                                        \
                dot_ = fmaf(qz, p_.z, dot_);                                        \
                const float d2_ = __fadd_rn(__fadd_rn(qq, p_.w),                    \
                                            -__fmul_rn(2.0f, dot_));                \
                const uint64_t key_ = ((uint64_t)flip_f32(d2_) << 16) | oid_;       \
                const bool p0_ = key_ < k0, p1_ = key_ < k1;                        \
                const bool p2_ = key_ < k2, p3_ = key_ < k3;                        \
                k3 = p3_ ? (p2_ ? k2 : key_) : k3;                                  \
                k2 = p2_ ? (p1_ ? k1 : key_) : k2;                                  \
                k1 = p1_ ? (p0_ ? k0 : key_) : k1;                                  \
                k0 = p0_ ? key_ : k0;                                               \
            }                                                                       \
        }

        // Chebyshev <= 1 cube (warp-uniform)
        {
            const int z0 = max(0, cz - 1), z1 = min(G - 1, cz + 1);
            const int y0 = max(0, cy - 1), y1 = min(G - 1, cy + 1);
            const int x0 = max(0, cx - 1), x1 = min(G - 1, cx + 1);
            for (int z = z0; z <= z1; z++)
                for (int y = y0; y <= y1; y++)
                    for (int x = x0; x <= x1; x++)
                        SCAN_CELL(x | (y << 3) | (z << 6));
        }

        // expanding shells; unprocessed cells at Chebyshev >= rad are at
        // distance >= (rad-1)*GH. Warp-vote exit.
        for (int rad = 2; rad < G; rad++) {
            const float dmin = (float)(rad - 1) * GH;
            const float bd3v = unflip_f32((uint32_t)(k3 >> 16));
            if (__all_sync(0xffffffffu, bd3v <= dmin * dmin)) break;
            const int z0 = max(0, cz - rad), z1 = min(G - 1, cz + rad);
            const int y0 = max(0, cy - rad), y1 = min(G - 1, cy + rad);
            const int x0 = max(0, cx - rad), x1 = min(G - 1, cx + rad);
            for (int z = z0; z <= z1; z++) {
                const int az = abs(z - cz);
                for (int y = y0; y <= y1; y++) {
                    const int ay = abs(y - cy);
                    for (int x = x0; x <= x1; x++) {
                        const int ax = abs(x - cx);
                        if (max(ax, max(ay, az)) == rad)
                            SCAN_CELL(x | (y << 3) | (z << 6));
                    }
                }
            }
        }
        #undef SCAN_CELL

        if (active) {
            const float d0 = unflip_f32((uint32_t)(k0 >> 16));
            const float d1 = unflip_f32((uint32_t)(k1 >> 16));
            const float d2v = unflip_f32((uint32_t)(k2 >> 16));
            const float d3 = unflip_f32((uint32_t)(k3 >> 16));
            const float w0 = 1.0f / fmaxf(d0, 1e-16f);
            const float w1 = 1.0f / fmaxf(d1, 1e-16f);
            const float w2 = 1.0f / fmaxf(d2v, 1e-16f);
            const float w3 = 1.0f / fmaxf(d3, 1e-16f);
            const float inv = 1.0f / (((w0 + w1) + w2) + w3);
            g_knn_idx[r * 4 + 0] = (int)(k0 & 0xFFFFu);
            g_knn_idx[r * 4 + 1] = (int)(k1 & 0xFFFFu);
            g_knn_idx[r * 4 + 2] = (int)(k2 & 0xFFFFu);
            g_knn_idx[r * 4 + 3] = (int)(k3 & 0xFFFFu);
            g_knn_w[r * 4 + 0] = w0 * inv;
            g_knn_w[r * 4 + 1] = w1 * inv;
            g_knn_w[r * 4 + 2] = w2 * inv;
            g_knn_w[r * 4 + 3] = w3 * inv;
        }
    }
}

// ---------------------------------------------------------------------------
// Tensor-core GEMM (mma.sync bf16, hi/lo split) + BN + ReLU (+ gather/add).
// CTA: 128x128, 8 warps (warp tile 32m x 64n), BK=32. (unchanged from R6)
// ---------------------------------------------------------------------------
#define ROWB 80   // smem row pitch in bytes (32 bf16 = 64 B data + 16 B pad)

template <int KDIM, bool FUSED>
__global__ void __launch_bounds__(256) gemm_mma(
    const float* __restrict__ A,
    const __nv_bfloat16* __restrict__ Whi,
    const __nv_bfloat16* __restrict__ Wlo,
    const float* __restrict__ bias,
    const float* __restrict__ gamma,
    const float* __restrict__ beta,
    const float* __restrict__ mean,
    const float* __restrict__ var,
    float* __restrict__ outp)
{
    __shared__ __align__(16) uint8_t sAh[128 * ROWB];
    __shared__ __align__(16) uint8_t sAl[128 * ROWB];
    __shared__ __align__(16) uint8_t sBh[128 * ROWB];
    __shared__ __align__(16) uint8_t sBl[128 * ROWB];
    __shared__ float scale_s[C_OUT];
    __shared__ float shift_s[C_OUT];

    const int tid  = threadIdx.x;
    const int wid  = tid >> 5;
    const int lane = tid & 31;
    const int wm   = wid & 3;
    const int wn   = wid >> 2;
    const int row0 = blockIdx.x * 128;

    if (tid < C_OUT) {
        const float s = gamma[tid] * rsqrtf(var[tid] + 1e-5f);
        scale_s[tid] = s;
        shift_s[tid] = beta[tid] + (bias[tid] - mean[tid]) * s;
    }

    float acc[2][8][4];
    #pragma unroll
    for (int mt = 0; mt < 2; mt++)
        #pragma unroll
        for (int nt = 0; nt < 8; nt++)
            #pragma unroll
            for (int c = 0; c < 4; c++) acc[mt][nt][c] = 0.0f;

    const uint32_t sAh_b = smem_u32(sAh), sAl_b = smem_u32(sAl);
    const uint32_t sBh_b = smem_u32(sBh), sBl_b = smem_u32(sBl);
    const int a_row  = wm * 32 + (lane & 7) + ((lane >> 3) & 1) * 8;
    const int a_kby  = ((lane >> 4) & 1) * 16;
    const int b_nrow = wn * 64 + (lane & 7) + ((lane >> 4) & 1) * 8;
    const int b_kby  = ((lane >> 3) & 1) * 16;

    const int rr   = tid >> 1;
    const int half = tid & 1;

    for (int kc = 0; kc < KDIM / 32; kc++) {
        const int kt = kc * 32;

        {
            const float* ap = A + (size_t)(row0 + rr) * KDIM + kt + half * 16;
            const uint32_t wb = rr * ROWB + half * 32;
            #pragma unroll
            for (int q = 0; q < 2; q++) {
                const float4 v0 = *(const float4*)(ap + q * 8);
                const float4 v1 = *(const float4*)(ap + q * 8 + 4);
                __nv_bfloat162 h0 = __floats2bfloat162_rn(v0.x, v0.y);
                __nv_bfloat162 h1 = __floats2bfloat162_rn(v0.z, v0.w);
                __nv_bfloat162 h2 = __floats2bfloat162_rn(v1.x, v1.y);
                __nv_bfloat162 h3 = __floats2bfloat162_rn(v1.z, v1.w);
                __nv_bfloat162 l0 = __floats2bfloat162_rn(v0.x - __bfloat162float(h0.x),
                                                          v0.y - __bfloat162float(h0.y));
                __nv_bfloat162 l1 = __floats2bfloat162_rn(v0.z - __bfloat162float(h1.x),
                                                          v0.w - __bfloat162float(h1.y));
                __nv_bfloat162 l2 = __floats2bfloat162_rn(v1.x - __bfloat162float(h2.x),
                                                          v1.y - __bfloat162float(h2.y));
                __nv_bfloat162 l3 = __floats2bfloat162_rn(v1.z - __bfloat162float(h3.x),
                                                          v1.w - __bfloat162float(h3.y));
                *(uint4*)(sAh + wb + q * 16) = make_uint4(
                    *(uint32_t*)&h0, *(uint32_t*)&h1, *(uint32_t*)&h2, *(uint32_t*)&h3);
                *(uint4*)(sAl + wb + q * 16) = make_uint4(
                    *(uint32_t*)&l0, *(uint32_t*)&l1, *(uint32_t*)&l2, *(uint32_t*)&l3);
            }
        }
        {
            const __nv_bfloat16* wh = Whi + (size_t)rr * KDIM + kt + half * 16;
            const __nv_bfloat16* wl = Wlo + (size_t)rr * KDIM + kt + half * 16;
            const uint32_t wb = rr * ROWB + half * 32;
            *(uint4*)(sBh + wb)      = *(const uint4*)(wh);
            *(uint4*)(sBh + wb + 16) = *(const uint4*)(wh + 8);
            *(uint4*)(sBl + wb)      = *(const uint4*)(wl);
            *(uint4*)(sBl + wb + 16) = *(const uint4*)(wl + 8);
        }
        __syncthreads();

        #pragma unroll
        for (int kk = 0; kk < 32; kk += 16) {
            uint32_t ah[2][4], al[2][4];
            #pragma unroll
            for (int mt = 0; mt < 2; mt++) {
                const uint32_t ao = (uint32_t)((a_row + mt * 16) * ROWB + kk * 2 + a_kby);
                LDSM_X4(ah[mt][0], ah[mt][1], ah[mt][2], ah[mt][3], sAh_b + ao);
                LDSM_X4(al[mt][0], al[mt][1], al[mt][2], al[mt][3], sAl_b + ao);
            }
            #pragma unroll
            for (int ntp = 0; ntp < 4; ntp++) {
                const uint32_t bo = (uint32_t)((b_nrow + ntp * 16) * ROWB + kk * 2 + b_kby);
                uint32_t bh0, bh1, bh2, bh3, bl0, bl1, bl2, bl3;
                LDSM_X4(bh0, bh1, bh2, bh3, sBh_b + bo);
                LDSM_X4(bl0, bl1, bl2, bl3, sBl_b + bo);
                #pragma unroll
                for (int mt = 0; mt < 2; mt++) {
                    mma_bf16(acc[mt][ntp * 2 + 0], ah[mt], bh0, bh1);
                    mma_bf16(acc[mt][ntp * 2 + 0], al[mt], bh0, bh1);
                    mma_bf16(acc[mt][ntp * 2 + 1], ah[mt], bh2, bh3);
                    mma_bf16(acc[mt][ntp * 2 + 1], al[mt], bh2, bh3);
                    mma_bf16(acc[mt][ntp * 2 + 0], ah[mt], bl0, bl1);
                    mma_bf16(acc[mt][ntp * 2 + 1], ah[mt], bl2, bl3);
                }
            }
        }
        __syncthreads();
    }

    float* dst = FUSED ? outp : g_xd;
    const int quad = lane >> 2;
    const int tq2  = (lane & 3) * 2;

    #pragma unroll
    for (int mt = 0; mt < 2; mt++) {
        #pragma unroll
        for (int h = 0; h < 2; h++) {
            const int r = row0 + wm * 32 + mt * 16 + quad + h * 8;

            const float* fr[KNN];
            float wk[KNN];
            if (FUSED) {
                const int bidx = r >> 14;
                const float* xdb = g_xd + (size_t)bidx * N_DOWN * C_OUT;
                #pragma unroll
                for (int k = 0; k < KNN; k++) {
                    fr[k] = xdb + (size_t)g_knn_idx[r * 4 + k] * C_OUT;
                    wk[k] = g_knn_w[r * 4 + k];
                }
            }

            #pragma unroll
            for (int nt = 0; nt < 8; nt++) {
                const int col = wn * 64 + nt * 8 + tq2;
                float o0 = fmaxf(fmaf(acc[mt][nt][h * 2 + 0], scale_s[col],     shift_s[col]),     0.0f);
                float o1 = fmaxf(fmaf(acc[mt][nt][h * 2 + 1], scale_s[col + 1], shift_s[col + 1]), 0.0f);
                if (FUSED) {
                    #pragma unroll
                    for (int k = 0; k < KNN; k++) {
                        const float2 v = *(const float2*)(fr[k] + col);
                        o0 = fmaf(wk[k], v.x, o0);
                        o1 = fmaf(wk[k], v.y, o1);
                    }
                }
                *(float2*)(dst + (size_t)r * C_OUT + col) = make_float2(o0, o1);
            }
        }
    }
}

// ---------------------------------------------------------------------------
// Launch
// ---------------------------------------------------------------------------
extern "C" void kernel_launch(void* const* d_in, const int* in_sizes, int n_in,
                              void* d_out, int out_size)
{
    const float* x_down  = (const float*)d_in[0];
    const float* x_up    = (const float*)d_in[1];
    const float* p_down  = (const float*)d_in[2];
    const float* p_up    = (const float*)d_in[3];
    const float* W_down  = (const float*)d_in[4];
    const float* b_down  = (const float*)d_in[5];
    const float* g_down  = (const float*)d_in[6];
    const float* be_down = (const float*)d_in[7];
    const float* m_down  = (const float*)d_in[8];
    const float* v_down  = (const float*)d_in[9];
    const float* W_up    = (const float*)d_in[10];
    const float* b_up    = (const float*)d_in[11];
    const float* g_up    = (const float*)d_in[12];
    const float* be_up   = (const float*)d_in[13];
    const float* m_up    = (const float*)d_in[14];
    const float* v_up    = (const float*)d_in[15];
    float* out = (float*)d_out;

    int* cs;  cudaGetSymbolAddress((void**)&cs, g_cellstart);
    int* qcs; cudaGetSymbolAddress((void**)&qcs, g_qcellstart);
    unsigned short* qid; cudaGetSymbolAddress((void**)&qid, g_qid);
    __nv_bfloat16 *wdh, *wdl, *wuh, *wul;
    cudaGetSymbolAddress((void**)&wdh, g_Wd_hi);
    cudaGetSymbolAddress((void**)&wdl, g_Wd_lo);
    cudaGetSymbolAddress((void**)&wuh, g_Wu_hi);
    cudaGetSymbolAddress((void**)&wul, g_Wu_lo);

    // 0) weight transpose + split
    prep_weights<<<(C_OUT * C_IN + C_OUT * C_OUT + 255) / 256, 256>>>(W_down, W_up);

    // 1) spatial grids + kNN (no smem; warp per cell)
    build_grid<N_DOWN, true ><<<B_SZ, 512>>>(p_down, cs,  nullptr);
    build_grid<N_UP,   false><<<B_SZ, 512>>>(p_up,   qcs, qid);
    dim3 qgrid(NCELL / 4, B_SZ);
    knn_query<<<qgrid, 128>>>(p_up);

    // 2) down MLP -> g_xd  (tensor cores, M=16384, K=256)
    gemm_mma<C_IN, false><<<M_DOWN / 128, 256>>>(
        x_down, wdh, wdl, b_down, g_down, be_down, m_down, v_down, nullptr);

    // 3) up MLP + gather + add -> out  (tensor cores, M=65536, K=128)
    gemm_mma<C_OUT, true><<<M_UP / 128, 256>>>(
        x_up, wuh, wul, b_up, g_up, be_up, m_up, v_up, out);
}